// round 15
// baseline (speedup 1.0000x reference)
#include <cuda_runtime.h>
#include <cuda_fp16.h>
#include <cstdint>

// ---------------- problem constants ----------------
#define BB      2
#define LL      2048
#define DMODEL  1024
#define DINNER  2048
#define NSTATE  16
#define NTOK    (BB*LL)      // 4096 tokens

// ---------------- device scratch (allocation-free rule: __device__ globals) ----------------
__device__ __half  g_xz  [(size_t)NTOK * 4096];         // in_proj output, fp16 [tok][4096] (xs|z)
__device__ float   g_bc  [(size_t)NTOK * 32];           // x_proj output (cols 0..15 B, 16..31 C)
__device__ float   g_bcp [(size_t)8 * NTOK * 32];       // x_proj split-K partials
__device__ __half  g_x1   [(size_t)NTOK * DMODEL];      // fp16 x
__device__ __half  g_win1 [(size_t)4096 * DMODEL];      // fp16 in_proj_w
__device__ __half  g_wxp1 [(size_t)128  * DINNER];      // fp16 x_proj_w (rows 0..31 used)
__device__ __half  g_wout1[(size_t)1024 * DINNER];      // fp16 out_proj_w
__device__ __half  g_xs1  [(size_t)NTOK * DINNER];      // fp16 xs (conv output; feeds xproj AND scan)
__device__ __half  g_y1   [(size_t)NTOK * DINNER];      // fp16 final y (written by scan)

// ---------------- asm helpers ----------------
#define CP_ASYNC16(dst, src) \
    asm volatile("cp.async.cg.shared.global [%0], [%1], 16;\n" :: "r"(dst), "l"(src))
#define CP_ASYNC8(dst, src) \
    asm volatile("cp.async.ca.shared.global [%0], [%1], 8;\n" :: "r"(dst), "l"(src))
#define CP_COMMIT() asm volatile("cp.async.commit_group;\n")
#define CP_WAIT(n)  asm volatile("cp.async.wait_group %0;\n" :: "n"(n))
#define LDSM4(r0, r1, r2, r3, addr) \
    asm volatile("ldmatrix.sync.aligned.m8n8.x4.shared.b16 {%0,%1,%2,%3}, [%4];" \
                 : "=r"(r0), "=r"(r1), "=r"(r2), "=r"(r3) : "r"(addr))

__device__ __forceinline__ uint32_t smem_u32(const void* p)
{
    return (uint32_t)__cvta_generic_to_shared(p);
}

// ---------------- fused fp32 -> fp16 conversion of all operands (one launch) ----------------
#define CVT_S0 (NTOK * DMODEL / 2)
#define CVT_S1 (CVT_S0 + 4096 * DMODEL / 2)
#define CVT_S2 (CVT_S1 + 32 * DINNER / 2)
#define CVT_S3 (CVT_S2 + 1024 * DINNER / 2)

__global__ void cvt_all_kernel(const float* __restrict__ x, const float* __restrict__ in_w,
                               const float* __restrict__ xp_w, const float* __restrict__ out_w,
                               __half* __restrict__ x1, __half* __restrict__ win1,
                               __half* __restrict__ wxp1, __half* __restrict__ wout1)
{
    int i = blockIdx.x * blockDim.x + threadIdx.x;
    if (i >= CVT_S3) return;
    const float* src;
    __half2* dst;
    if (i < CVT_S0)      { src = x;     dst = (__half2*)x1;    /* i */ }
    else if (i < CVT_S1) { src = in_w;  dst = (__half2*)win1;  i -= CVT_S0; }
    else if (i < CVT_S2) { src = xp_w;  dst = (__half2*)wxp1;  i -= CVT_S1; }
    else                 { src = out_w; dst = (__half2*)wout1; i -= CVT_S2; }
    float2 v = reinterpret_cast<const float2*>(src)[i];
    dst[i] = __floats2half2_rn(v.x, v.y);
}

// ---------------- fp16 mma helpers ----------------
__device__ __forceinline__ void mma16816(float* c, const uint32_t* a, const uint32_t* b)
{
    asm volatile(
        "mma.sync.aligned.m16n8k16.row.col.f32.f16.f16.f32 "
        "{%0,%1,%2,%3}, {%4,%5,%6,%7}, {%8,%9}, {%0,%1,%2,%3};"
        : "+f"(c[0]), "+f"(c[1]), "+f"(c[2]), "+f"(c[3])
        : "r"(a[0]), "r"(a[1]), "r"(a[2]), "r"(a[3]), "r"(b[0]), "r"(b[1]));
}

#define APITCH 144               // bytes per 64-half row (64 + 8 pad), 16B-aligned
#define A_STAGE  (128 * APITCH)  // 18432 B (128-row tile)
#define A64_STAGE (64 * APITCH)  // 9216 B  (64-row tile)

// ---------------- GEMM 128x128 tile, BK=64, 3-stage cp.async, occupancy 2 ----------------
// C[M,N] = A[M,K] * B[N,K]^T. Used for out_proj (fits one wave).
template<int HALF_OUT>
__global__ __launch_bounds__(256, 2) void gemm_t128(
    const __half* __restrict__ A, const __half* __restrict__ B,
    void* __restrict__ Cv, int M, int N, int K)
{
    extern __shared__ char sm[];
    const uint32_t sA = smem_u32(sm);                 // 3 stages A
    const uint32_t sB = sA + 3 * A_STAGE;             // 3 stages B

    const int tid  = threadIdx.x;
    const int lane = tid & 31;
    const int wid  = tid >> 5;
    const int wm   = wid & 1;        // 2 warps along M (64 each)
    const int wn   = wid >> 1;       // 4 warps along N (32 each)
    const int grp  = lane >> 2;
    const int tig  = lane & 3;
    const size_t bm = (size_t)blockIdx.y * 128;
    const size_t bn = (size_t)blockIdx.x * 128;

    uint32_t gA[4], gB[4], sO[4];
    #pragma unroll
    for (int i = 0; i < 4; i++) {
        int ch = tid + i * 256;
        int r = ch >> 3, c = ch & 7;
        gA[i] = (uint32_t)((bm + r) * K + c * 8);
        gB[i] = (uint32_t)((bn + r) * K + c * 8);
        sO[i] = (uint32_t)(r * APITCH + c * 16);
    }

    float acc[4][4][4];
    #pragma unroll
    for (int i = 0; i < 4; i++)
        #pragma unroll
        for (int j = 0; j < 4; j++)
            #pragma unroll
            for (int q = 0; q < 4; q++) acc[i][j][q] = 0.0f;

    const int nIter = K >> 6;

    #pragma unroll
    for (int s = 0; s < 2; s++) {
        const uint32_t k0 = (uint32_t)s << 6;
        #pragma unroll
        for (int i = 0; i < 4; i++) {
            CP_ASYNC16(sA + s * A_STAGE + sO[i], A + gA[i] + k0);
            CP_ASYNC16(sB + s * A_STAGE + sO[i], B + gB[i] + k0);
        }
        CP_COMMIT();
    }

    const int a_r  = lane & 15;
    const int a_c  = (lane >> 4) << 3;
    const int b_m4 = lane >> 3;
    const int b_fnp = b_m4 >> 1;
    const int b_kk  = (b_m4 & 1) << 3;
    const int b_rr  = lane & 7;

    int cur = 0;
    for (int it = 0; it < nIter; it++) {
        if (it + 1 < nIter) { CP_WAIT(1); } else { CP_WAIT(0); }
        __syncthreads();

        if (it + 2 < nIter) {
            const int s2 = (it + 2) % 3;
            const uint32_t k2 = (uint32_t)(it + 2) << 6;
            #pragma unroll
            for (int i = 0; i < 4; i++) {
                CP_ASYNC16(sA + s2 * A_STAGE + sO[i], A + gA[i] + k2);
                CP_ASYNC16(sB + s2 * A_STAGE + sO[i], B + gB[i] + k2);
            }
            CP_COMMIT();
        }

        const uint32_t aBase = sA + cur * A_STAGE;
        const uint32_t bBase = sB + cur * A_STAGE;
        #pragma unroll
        for (int s = 0; s < 4; s++) {
            const int kb = s * 16;
            uint32_t af[4][4];
            uint32_t bfr[2][4];
            #pragma unroll
            for (int fm = 0; fm < 4; fm++) {
                uint32_t ad = aBase + (wm * 64 + fm * 16 + a_r) * APITCH + (kb + a_c) * 2;
                LDSM4(af[fm][0], af[fm][1], af[fm][2], af[fm][3], ad);
            }
            #pragma unroll
            for (int p = 0; p < 2; p++) {
                uint32_t bd = bBase + (wn * 32 + p * 16 + b_fnp * 8 + b_rr) * APITCH + (kb + b_kk) * 2;
                LDSM4(bfr[p][0], bfr[p][1], bfr[p][2], bfr[p][3], bd);
            }
            #pragma unroll
            for (int fm = 0; fm < 4; fm++)
                #pragma unroll
                for (int fn = 0; fn < 4; fn++)
                    mma16816(acc[fm][fn], af[fm], &bfr[fn >> 1][(fn & 1) * 2]);
        }
        cur = (cur + 1) % 3;
    }

    #pragma unroll
    for (int fm = 0; fm < 4; fm++) {
        #pragma unroll
        for (int fn = 0; fn < 4; fn++) {
            size_t r  = bm + wm * 64 + fm * 16 + grp;
            size_t cN = bn + wn * 32 + fn * 8 + tig * 2;
            if (HALF_OUT) {
                __half* C = (__half*)Cv;
                *reinterpret_cast<__half2*>(&C[r * N + cN]) =
                    __floats2half2_rn(acc[fm][fn][0], acc[fm][fn][1]);
                *reinterpret_cast<__half2*>(&C[(r + 8) * N + cN]) =
                    __floats2half2_rn(acc[fm][fn][2], acc[fm][fn][3]);
            } else {
                float* C = (float*)Cv;
                *reinterpret_cast<float2*>(&C[r * N + cN])       = make_float2(acc[fm][fn][0], acc[fm][fn][1]);
                *reinterpret_cast<float2*>(&C[(r + 8) * N + cN]) = make_float2(acc[fm][fn][2], acc[fm][fn][3]);
            }
        }
    }
}

// ---------------- GEMM 64x128 tile, BK=64, 3-stage, occ 2 (fp16 out) ----------------
// Finer M-granularity for in_proj: 2048 CTAs / 296 slots = 6.92 waves (~1% tail).
// 8 warps as 2(M,32 rows)x4(N,32 cols); acc 32 regs/thread.
__global__ __launch_bounds__(256, 2) void gemm_t64(
    const __half* __restrict__ A, const __half* __restrict__ B,
    __half* __restrict__ C, int M, int N, int K)
{
    extern __shared__ char sm[];
    const uint32_t sA = smem_u32(sm);                 // 3 stages A (64 rows)
    const uint32_t sB = sA + 3 * A64_STAGE;           // 3 stages B (128 rows)

    const int tid  = threadIdx.x;
    const int lane = tid & 31;
    const int wid  = tid >> 5;
    const int wm   = wid & 1;        // 2 warps along M (32 each)
    const int wn   = wid >> 1;       // 4 warps along N (32 each)
    const int grp  = lane >> 2;
    const int tig  = lane & 3;
    const size_t bm = (size_t)blockIdx.y * 64;
    const size_t bn = (size_t)blockIdx.x * 128;

    // A: 512 16B-chunks -> 2/thread; B: 1024 -> 4/thread
    uint32_t gA[2], oA[2], gB[4], oB[4];
    #pragma unroll
    for (int i = 0; i < 2; i++) {
        int ch = tid + i * 256;
        int r = ch >> 3, c = ch & 7;
        gA[i] = (uint32_t)((bm + r) * K + c * 8);
        oA[i] = (uint32_t)(r * APITCH + c * 16);
    }
    #pragma unroll
    for (int i = 0; i < 4; i++) {
        int ch = tid + i * 256;
        int r = ch >> 3, c = ch & 7;
        gB[i] = (uint32_t)((bn + r) * K + c * 8);
        oB[i] = (uint32_t)(r * APITCH + c * 16);
    }

    float acc[2][4][4];
    #pragma unroll
    for (int i = 0; i < 2; i++)
        #pragma unroll
        for (int j = 0; j < 4; j++)
            #pragma unroll
            for (int q = 0; q < 4; q++) acc[i][j][q] = 0.0f;

    const int nIter = K >> 6;

    #pragma unroll
    for (int s = 0; s < 2; s++) {
        const uint32_t k0 = (uint32_t)s << 6;
        #pragma unroll
        for (int i = 0; i < 2; i++) CP_ASYNC16(sA + s * A64_STAGE + oA[i], A + gA[i] + k0);
        #pragma unroll
        for (int i = 0; i < 4; i++) CP_ASYNC16(sB + s * A_STAGE + oB[i], B + gB[i] + k0);
        CP_COMMIT();
    }

    const int a_r  = lane & 15;
    const int a_c  = (lane >> 4) << 3;
    const int b_m4 = lane >> 3;
    const int b_fnp = b_m4 >> 1;
    const int b_kk  = (b_m4 & 1) << 3;
    const int b_rr  = lane & 7;

    int cur = 0;
    for (int it = 0; it < nIter; it++) {
        if (it + 1 < nIter) { CP_WAIT(1); } else { CP_WAIT(0); }
        __syncthreads();

        if (it + 2 < nIter) {
            const int s2 = (it + 2) % 3;
            const uint32_t k2 = (uint32_t)(it + 2) << 6;
            #pragma unroll
            for (int i = 0; i < 2; i++) CP_ASYNC16(sA + s2 * A64_STAGE + oA[i], A + gA[i] + k2);
            #pragma unroll
            for (int i = 0; i < 4; i++) CP_ASYNC16(sB + s2 * A_STAGE + oB[i], B + gB[i] + k2);
            CP_COMMIT();
        }

        const uint32_t aBase = sA + cur * A64_STAGE;
        const uint32_t bBase = sB + cur * A_STAGE;
        #pragma unroll
        for (int s = 0; s < 4; s++) {
            const int kb = s * 16;
            uint32_t af[2][4];
            uint32_t bfr[2][4];
            #pragma unroll
            for (int fm = 0; fm < 2; fm++) {
                uint32_t ad = aBase + (wm * 32 + fm * 16 + a_r) * APITCH + (kb + a_c) * 2;
                LDSM4(af[fm][0], af[fm][1], af[fm][2], af[fm][3], ad);
            }
            #pragma unroll
            for (int p = 0; p < 2; p++) {
                uint32_t bd = bBase + (wn * 32 + p * 16 + b_fnp * 8 + b_rr) * APITCH + (kb + b_kk) * 2;
                LDSM4(bfr[p][0], bfr[p][1], bfr[p][2], bfr[p][3], bd);
            }
            #pragma unroll
            for (int fm = 0; fm < 2; fm++)
                #pragma unroll
                for (int fn = 0; fn < 4; fn++)
                    mma16816(acc[fm][fn], af[fm], &bfr[fn >> 1][(fn & 1) * 2]);
        }
        cur = (cur + 1) % 3;
    }

    #pragma unroll
    for (int fm = 0; fm < 2; fm++) {
        #pragma unroll
        for (int fn = 0; fn < 4; fn++) {
            size_t r  = bm + wm * 32 + fm * 16 + grp;
            size_t cN = bn + wn * 32 + fn * 8 + tig * 2;
            *reinterpret_cast<__half2*>(&C[r * N + cN]) =
                __floats2half2_rn(acc[fm][fn][0], acc[fm][fn][1]);
            *reinterpret_cast<__half2*>(&C[(r + 8) * N + cN]) =
                __floats2half2_rn(acc[fm][fn][2], acc[fm][fn][3]);
        }
    }
}

// ---------------- x_proj split-K GEMM: Cp[ks][M][32] = A[M, ks-slice] * B[0:32, ks-slice]^T ----
#define XKS 8
#define XKSL (DINNER / XKS)     // 256
#define XB_STAGE (32 * APITCH)
__global__ __launch_bounds__(256, 2) void gemm_xproj(
    const __half* __restrict__ A, const __half* __restrict__ B, float* __restrict__ Cp)
{
    extern __shared__ char sm[];
    const uint32_t sA = smem_u32(sm);                 // [2][128][APITCH]
    const uint32_t sB = sA + 2 * A_STAGE;             // [2][32][APITCH]

    const int tid  = threadIdx.x;
    const int lane = tid & 31;
    const int wid  = tid >> 5;                        // 8 warps, 16 rows each
    const int grp  = lane >> 2;
    const int tig  = lane & 3;
    const size_t bm = (size_t)blockIdx.y * 128;
    const int ks   = blockIdx.x;
    const int kb0  = ks * XKSL;

    uint32_t gA[4], oA[4];
    #pragma unroll
    for (int i = 0; i < 4; i++) {
        int ch = tid + i * 256;
        int r = ch >> 3, c = ch & 7;
        gA[i] = (uint32_t)((bm + r) * DINNER + kb0 + c * 8);
        oA[i] = (uint32_t)(r * APITCH + c * 16);
    }
    const int rB = tid >> 3, cB = tid & 7;
    const uint32_t gBo = (uint32_t)(rB * DINNER + kb0 + cB * 8);
    const uint32_t oBo = (uint32_t)(rB * APITCH + cB * 16);

    float acc[4][4];
    #pragma unroll
    for (int j = 0; j < 4; j++)
        #pragma unroll
        for (int q = 0; q < 4; q++) acc[j][q] = 0.0f;

    const int nIter = XKSL >> 6;                      // 4

    #pragma unroll
    for (int i = 0; i < 4; i++) CP_ASYNC16(sA + oA[i], A + gA[i]);
    CP_ASYNC16(sB + oBo, B + gBo);
    CP_COMMIT();

    const int a_r  = lane & 15;
    const int a_c  = (lane >> 4) << 3;
    const int b_m4 = lane >> 3;
    const int b_fnp = b_m4 >> 1;
    const int b_kk  = (b_m4 & 1) << 3;
    const int b_rr  = lane & 7;

    for (int it = 0; it < nIter; it++) {
        const int st = it & 1;
        if (it + 1 < nIter) {
            const uint32_t k1 = (uint32_t)(it + 1) << 6;
            #pragma unroll
            for (int i = 0; i < 4; i++)
                CP_ASYNC16(sA + (st ^ 1) * A_STAGE + oA[i], A + gA[i] + k1);
            CP_ASYNC16(sB + (st ^ 1) * XB_STAGE + oBo, B + gBo + k1);
            CP_COMMIT();
            CP_WAIT(1);
        } else {
            CP_WAIT(0);
        }
        __syncthreads();

        const uint32_t aBase = sA + st * A_STAGE;
        const uint32_t bBase = sB + st * XB_STAGE;
        #pragma unroll
        for (int s = 0; s < 4; s++) {
            const int kb = s * 16;
            uint32_t af[4];
            uint32_t bfr[2][4];
            uint32_t ad = aBase + (wid * 16 + a_r) * APITCH + (kb + a_c) * 2;
            LDSM4(af[0], af[1], af[2], af[3], ad);
            #pragma unroll
            for (int p = 0; p < 2; p++) {
                uint32_t bd = bBase + (p * 16 + b_fnp * 8 + b_rr) * APITCH + (kb + b_kk) * 2;
                LDSM4(bfr[p][0], bfr[p][1], bfr[p][2], bfr[p][3], bd);
            }
            #pragma unroll
            for (int fn = 0; fn < 4; fn++)
                mma16816(acc[fn], af, &bfr[fn >> 1][(fn & 1) * 2]);
        }
        __syncthreads();
    }

    float* Co = Cp + (size_t)ks * NTOK * 32;
    #pragma unroll
    for (int fn = 0; fn < 4; fn++) {
        size_t r = bm + wid * 16 + grp;
        int   c  = fn * 8 + tig * 2;
        *reinterpret_cast<float2*>(&Co[r * 32 + c])       = make_float2(acc[fn][0], acc[fn][1]);
        *reinterpret_cast<float2*>(&Co[(r + 8) * 32 + c]) = make_float2(acc[fn][2], acc[fn][3]);
    }
}

// sum the 8 split-K partials -> g_bc
__global__ void reduce_bc_kernel(const float* __restrict__ Cp, float* __restrict__ bc)
{
    const int n4 = NTOK * 32 / 4;
    int i = blockIdx.x * blockDim.x + threadIdx.x;
    if (i >= n4) return;
    const float4* p = reinterpret_cast<const float4*>(Cp);
    float4 o = p[i];
    #pragma unroll
    for (int k = 1; k < XKS; k++) {
        float4 v = p[i + (size_t)k * n4];
        o.x += v.x; o.y += v.y; o.z += v.z; o.w += v.w;
    }
    reinterpret_cast<float4*>(bc)[i] = o;
}

// ---------------- depthwise causal conv1d (k=4) + silu ----------------
// 4 tokens x 4 channels per thread: 7 row-reads for 16 outputs.
__global__ void conv_silu_kernel(const __half* __restrict__ xz, const float* __restrict__ cw,
                                 const float* __restrict__ cb, __half* __restrict__ xs1)
{
    int i = blockIdx.x * blockDim.x + threadIdx.x;       // [tok-group(4)][chan-group(4)]
    if (i >= (NTOK / 4) * (DINNER / 4)) return;
    const int tg  = i >> 9;                              // token group (0..1023)
    const int d4  = (i & 511) << 2;                      // channel base
    const int tok0 = tg << 2;                            // first token of group
    const int l0   = tok0 & (LL - 1);                    // position in sequence

    float4 bias = *reinterpret_cast<const float4*>(cb + d4);
    const float4* cwv = reinterpret_cast<const float4*>(cw + d4 * 4);
    float4 w0 = cwv[0], w1 = cwv[1], w2 = cwv[2], w3 = cwv[3];
    const float* wp[4] = { reinterpret_cast<const float*>(&w0), reinterpret_cast<const float*>(&w1),
                           reinterpret_cast<const float*>(&w2), reinterpret_cast<const float*>(&w3) };

    float v[7][4];
    #pragma unroll
    for (int r = 0; r < 7; r++) {
        int lt = l0 - 3 + r;
        if (lt >= 0) {
            uint2 u = *reinterpret_cast<const uint2*>(xz + (size_t)(tok0 - 3 + r) * 4096 + d4);
            float2 a = __half22float2(*reinterpret_cast<const __half2*>(&u.x));
            float2 b = __half22float2(*reinterpret_cast<const __half2*>(&u.y));
            v[r][0] = a.x; v[r][1] = a.y; v[r][2] = b.x; v[r][3] = b.y;
        } else {
            v[r][0] = v[r][1] = v[r][2] = v[r][3] = 0.0f;
        }
    }

    #pragma unroll
    for (int t = 0; t < 4; t++) {
        float o[4];
        #pragma unroll
        for (int c = 0; c < 4; c++) {
            float acc = reinterpret_cast<const float*>(&bias)[c];
            #pragma unroll
            for (int k = 0; k < 4; k++)
                acc = fmaf(wp[c][k], v[t + k][c], acc);
            o[c] = acc / (1.0f + __expf(-acc));
        }
        __half2 h01 = __floats2half2_rn(o[0], o[1]);
        __half2 h23 = __floats2half2_rn(o[2], o[3]);
        uint2 u;
        u.x = *reinterpret_cast<const unsigned*>(&h01);
        u.y = *reinterpret_cast<const unsigned*>(&h23);
        *reinterpret_cast<uint2*>(xs1 + (size_t)(tok0 + t) * DINNER + d4) = u;
    }
}

// ---------------- chunked SSM scan + D skip + silu(z) gate, fp16 in/out ----------------
// dA = exp(-0.1*n) <= 0.905 -> truncation after 128 steps < 3e-5 of steady state.
// 16 chunks of 128 steps, 128-step warm-up. 512 CTAs x 128 thr.
#define SCHUNK 128
#define SWARM  128
__global__ __launch_bounds__(128) void scan_kernel(
    const __half* __restrict__ xs1, const __half* __restrict__ xz,
    const float* __restrict__ bc, const float* __restrict__ A_log,
    const float* __restrict__ Dparam, __half* __restrict__ y1)
{
    __shared__ float BCs[4][8][32];
    const int tid  = threadIdx.x;
    const int wid  = tid >> 5;
    const int lane = tid & 31;
    const int b     = blockIdx.x >> 8;
    const int rem   = blockIdx.x & 255;
    const int dblk  = rem >> 4;
    const int chunk = rem & 15;
    const int d = dblk * 128 + wid * 32 + lane;

    const int w0 = chunk * SCHUNK;
    const int t0 = chunk ? (w0 - SWARM) : 0;
    const int t1 = w0 + SCHUNK;

    unsigned long long dAP[8], hP[8];
    #pragma unroll
    for (int i = 0; i < 8; i++) {
        float a0 = __expf(-0.1f * __expf(A_log[d * 16 + 2 * i]));
        float a1 = __expf(-0.1f * __expf(A_log[d * 16 + 2 * i + 1]));
        asm("mov.b64 %0, {%1,%2};" : "=l"(dAP[i]) : "f"(a0), "f"(a1));
        hP[i] = 0ull;
    }
    const float Dv = Dparam[d];
    const float* bcb = bc + (size_t)b * LL * 32;
    float (*ring)[32] = BCs[wid];

    #pragma unroll
    for (int s = 0; s < 3; s++) {
        CP_ASYNC8(smem_u32(&ring[(t0 + 2 * s) & 7][0]) + lane * 8,
                  bcb + (size_t)(t0 + 2 * s) * 32 + lane * 2);
        CP_COMMIT();
    }

    const __half* xsp = xs1 + (size_t)b * LL * DINNER + d;
    const __half* zp  = xz  + (size_t)b * LL * 4096 + DINNER + d;
    __half* y1p = y1 + (size_t)b * LL * DINNER + d;

    float xv[4], zv[4];
    #pragma unroll
    for (int i = 0; i < 4; i++) {
        xv[i] = __half2float(__ldg(xsp + (size_t)(t0 + i) * DINNER));
        zv[i] = __half2float(__ldg(zp  + (size_t)(t0 + i) * 4096));
    }

    for (int t = t0; t < t1; t++) {
        if (!(t & 1)) {
            if (t + 6 < t1)
                CP_ASYNC8(smem_u32(&ring[(t + 6) & 7][0]) + lane * 8,
                          bcb + (size_t)(t + 6) * 32 + lane * 2);
            CP_COMMIT();
        }
        CP_WAIT(3);
        __syncwarp();

        const int rs = t & 3;
        const float xvc = xv[rs], zvc = zv[rs];
        if (t + 4 < t1) {
            xv[rs] = __half2float(__ldg(xsp + (size_t)(t + 4) * DINNER));
            zv[rs] = __half2float(__ldg(zp  + (size_t)(t + 4) * 4096));
        }

        const float s = 0.1f * xvc;
        unsigned long long sP;
        asm("mov.b64 %0, {%1,%2};" : "=l"(sP) : "f"(s), "f"(s));

        const int slot = t & 7;
        unsigned long long yP[4] = {0ull, 0ull, 0ull, 0ull};
        #pragma unroll
        for (int i = 0; i < 8; i++) {
            unsigned long long bP = *reinterpret_cast<const unsigned long long*>(&ring[slot][2 * i]);
            unsigned long long cP = *reinterpret_cast<const unsigned long long*>(&ring[slot][16 + 2 * i]);
            unsigned long long tP;
            asm("mul.rn.f32x2 %0, %1, %2;" : "=l"(tP) : "l"(sP), "l"(bP));
            asm("fma.rn.f32x2 %0, %1, %2, %3;" : "=l"(hP[i]) : "l"(dAP[i]), "l"(hP[i]), "l"(tP));
            asm("fma.rn.f32x2 %0, %1, %2, %3;" : "=l"(yP[i & 3]) : "l"(hP[i]), "l"(cP), "l"(yP[i & 3]));
        }

        if (t >= w0) {
            float y = 0.0f;
            #pragma unroll
            for (int i = 0; i < 4; i++) {
                float lo, hi;
                asm("mov.b64 {%0,%1}, %2;" : "=f"(lo), "=f"(hi) : "l"(yP[i]));
                y += lo + hi;
            }
            float sg = 1.0f / (1.0f + __expf(-zvc));
            float yv = fmaf(xvc, Dv, y) * (zvc * sg);
            y1p[(size_t)t * DINNER] = __float2half(yv);
        }
    }
}

// ---------------- launch ----------------
extern "C" void kernel_launch(void* const* d_in, const int* in_sizes, int n_in,
                              void* d_out, int out_size)
{
    (void)in_sizes; (void)n_in; (void)out_size;
    const float* x      = (const float*)d_in[0];
    const float* in_w   = (const float*)d_in[1];
    const float* conv_w = (const float*)d_in[2];
    const float* conv_b = (const float*)d_in[3];
    const float* xp_w   = (const float*)d_in[4];
    const float* A_log  = (const float*)d_in[5];
    const float* Dp     = (const float*)d_in[6];
    const float* out_w  = (const float*)d_in[7];

    void *p_xz, *p_bc, *p_bcp, *p_x1, *p_win1, *p_wxp1, *p_wout1, *p_xs1, *p_y1;
    cudaGetSymbolAddress(&p_xz,    g_xz);
    cudaGetSymbolAddress(&p_bc,    g_bc);
    cudaGetSymbolAddress(&p_bcp,   g_bcp);
    cudaGetSymbolAddress(&p_x1,    g_x1);
    cudaGetSymbolAddress(&p_win1,  g_win1);
    cudaGetSymbolAddress(&p_wxp1,  g_wxp1);
    cudaGetSymbolAddress(&p_wout1, g_wout1);
    cudaGetSymbolAddress(&p_xs1,   g_xs1);
    cudaGetSymbolAddress(&p_y1,    g_y1);

    const int SMEMG   = 6 * A_STAGE;                      // 110592 (t128, occ 2)
    const int SMEMG64 = 3 * (A64_STAGE + A_STAGE);        // 82944  (t64,  occ 2)
    const int SMEMXP  = 2 * A_STAGE + 2 * XB_STAGE;       // 46080
    static int smem_set = 0;
    if (!smem_set) {
        cudaFuncSetAttribute(gemm_t128<1>, cudaFuncAttributeMaxDynamicSharedMemorySize, SMEMG);
        cudaFuncSetAttribute(gemm_t128<0>, cudaFuncAttributeMaxDynamicSharedMemorySize, SMEMG);
        cudaFuncSetAttribute(gemm_t64,     cudaFuncAttributeMaxDynamicSharedMemorySize, SMEMG64);
        cudaFuncSetAttribute(gemm_xproj,   cudaFuncAttributeMaxDynamicSharedMemorySize, SMEMXP);
        smem_set = 1;
    }

    const int T = 256;

    // all fp16 conversions in one launch
    cvt_all_kernel<<<(CVT_S3 + T - 1) / T, T>>>(x, in_w, xp_w, out_w,
                                                (__half*)p_x1, (__half*)p_win1,
                                                (__half*)p_wxp1, (__half*)p_wout1);

    // in_proj: [4096,1024] x [4096,1024]^T -> xz [4096,4096] (fp16 out, 64-row tiles)
    gemm_t64<<<dim3(4096 / 128, NTOK / 64), 256, SMEMG64>>>(
        (const __half*)p_x1, (const __half*)p_win1, (__half*)p_xz,
        NTOK, 4096, DMODEL);

    // depthwise causal conv + silu (4 tokens x 4 channels per thread)
    conv_silu_kernel<<<((NTOK / 4) * (DINNER / 4)) / 256, 256>>>(
        (const __half*)p_xz, conv_w, conv_b, (__half*)p_xs1);

    // x_proj: split-K=8, N=32 tile -> partials, then reduce
    gemm_xproj<<<dim3(XKS, NTOK / 128), 256, SMEMXP>>>(
        (const __half*)p_xs1, (const __half*)p_wxp1, (float*)p_bcp);
    reduce_bc_kernel<<<(NTOK * 32 / 4 + T - 1) / T, T>>>((const float*)p_bcp, (float*)p_bc);

    // chunked SSM scan fused with D skip, silu(z) gate (fp16 xs/z inputs)
    scan_kernel<<<512, 128>>>((const __half*)p_xs1, (const __half*)p_xz, (const float*)p_bc,
                              A_log, Dp, (__half*)p_y1);

    // out_proj: [4096,2048] x [1024,2048]^T -> out [4096,1024] (fp32 output)
    gemm_t128<0><<<dim3(1024 / 128, NTOK / 128), 256, SMEMG>>>(
        (const __half*)p_y1, (const __half*)p_wout1, d_out,
        NTOK, 1024, DINNER);
}

// round 16
// speedup vs baseline: 1.0543x; 1.0543x over previous
#include <cuda_runtime.h>
#include <cuda_fp16.h>
#include <cstdint>

// ---------------- problem constants ----------------
#define BB      2
#define LL      2048
#define DMODEL  1024
#define DINNER  2048
#define NSTATE  16
#define NTOK    (BB*LL)      // 4096 tokens

// ---------------- device scratch (allocation-free rule: __device__ globals) ----------------
__device__ __half  g_xz  [(size_t)NTOK * 4096];         // in_proj output, fp16 [tok][4096] (xs|z)
__device__ float   g_bc  [(size_t)NTOK * 32];           // x_proj output (cols 0..15 B, 16..31 C)
__device__ float   g_bcp [(size_t)8 * NTOK * 32];       // x_proj split-K partials
__device__ __half  g_x1   [(size_t)NTOK * DMODEL];      // fp16 x
__device__ __half  g_win1 [(size_t)4096 * DMODEL];      // fp16 in_proj_w
__device__ __half  g_wxp1 [(size_t)128  * DINNER];      // fp16 x_proj_w (rows 0..31 used)
__device__ __half  g_wout1[(size_t)1024 * DINNER];      // fp16 out_proj_w
__device__ __half  g_xs1  [(size_t)NTOK * DINNER];      // fp16 xs (conv output; feeds xproj AND scan)
__device__ __half  g_y1   [(size_t)NTOK * DINNER];      // fp16 final y (written by scan)

// ---------------- asm helpers ----------------
#define CP_ASYNC16(dst, src) \
    asm volatile("cp.async.cg.shared.global [%0], [%1], 16;\n" :: "r"(dst), "l"(src))
#define CP_ASYNC8(dst, src) \
    asm volatile("cp.async.ca.shared.global [%0], [%1], 8;\n" :: "r"(dst), "l"(src))
#define CP_COMMIT() asm volatile("cp.async.commit_group;\n")
#define CP_WAIT(n)  asm volatile("cp.async.wait_group %0;\n" :: "n"(n))
#define LDSM4(r0, r1, r2, r3, addr) \
    asm volatile("ldmatrix.sync.aligned.m8n8.x4.shared.b16 {%0,%1,%2,%3}, [%4];" \
                 : "=r"(r0), "=r"(r1), "=r"(r2), "=r"(r3) : "r"(addr))

__device__ __forceinline__ uint32_t smem_u32(const void* p)
{
    return (uint32_t)__cvta_generic_to_shared(p);
}

// ---------------- fused fp32 -> fp16 conversion of all operands (one launch) ----------------
#define CVT_S0 (NTOK * DMODEL / 2)
#define CVT_S1 (CVT_S0 + 4096 * DMODEL / 2)
#define CVT_S2 (CVT_S1 + 32 * DINNER / 2)
#define CVT_S3 (CVT_S2 + 1024 * DINNER / 2)

__global__ void cvt_all_kernel(const float* __restrict__ x, const float* __restrict__ in_w,
                               const float* __restrict__ xp_w, const float* __restrict__ out_w,
                               __half* __restrict__ x1, __half* __restrict__ win1,
                               __half* __restrict__ wxp1, __half* __restrict__ wout1)
{
    int i = blockIdx.x * blockDim.x + threadIdx.x;
    if (i >= CVT_S3) return;
    const float* src;
    __half2* dst;
    if (i < CVT_S0)      { src = x;     dst = (__half2*)x1;    /* i */ }
    else if (i < CVT_S1) { src = in_w;  dst = (__half2*)win1;  i -= CVT_S0; }
    else if (i < CVT_S2) { src = xp_w;  dst = (__half2*)wxp1;  i -= CVT_S1; }
    else                 { src = out_w; dst = (__half2*)wout1; i -= CVT_S2; }
    float2 v = reinterpret_cast<const float2*>(src)[i];
    dst[i] = __floats2half2_rn(v.x, v.y);
}

// ---------------- fp16 mma helpers ----------------
__device__ __forceinline__ void mma16816(float* c, const uint32_t* a, const uint32_t* b)
{
    asm volatile(
        "mma.sync.aligned.m16n8k16.row.col.f32.f16.f16.f32 "
        "{%0,%1,%2,%3}, {%4,%5,%6,%7}, {%8,%9}, {%0,%1,%2,%3};"
        : "+f"(c[0]), "+f"(c[1]), "+f"(c[2]), "+f"(c[3])
        : "r"(a[0]), "r"(a[1]), "r"(a[2]), "r"(a[3]), "r"(b[0]), "r"(b[1]));
}

#define APITCH 144               // bytes per 64-half row (64 + 8 pad), 16B-aligned
#define A_STAGE  (128 * APITCH)  // 18432 B (128-row tile)

// ---------------- GEMM 128x128 tile, BK=64, 3-stage cp.async, occupancy 2 ----------------
// C[M,N] = A[M,K] * B[N,K]^T. M%128==0, N%128==0, K%64==0, K/64 >= 2.
// HALF_OUT=1: C is __half*, else float*.  (FROZEN: converged config, R9/R15 experiments)
template<int HALF_OUT>
__global__ __launch_bounds__(256, 2) void gemm_t128(
    const __half* __restrict__ A, const __half* __restrict__ B,
    void* __restrict__ Cv, int M, int N, int K)
{
    extern __shared__ char sm[];
    const uint32_t sA = smem_u32(sm);                 // 3 stages A
    const uint32_t sB = sA + 3 * A_STAGE;             // 3 stages B

    const int tid  = threadIdx.x;
    const int lane = tid & 31;
    const int wid  = tid >> 5;
    const int wm   = wid & 1;        // 2 warps along M (64 each)
    const int wn   = wid >> 1;       // 4 warps along N (32 each)
    const int grp  = lane >> 2;
    const int tig  = lane & 3;
    const size_t bm = (size_t)blockIdx.y * 128;
    const size_t bn = (size_t)blockIdx.x * 128;

    uint32_t gA[4], gB[4], sO[4];
    #pragma unroll
    for (int i = 0; i < 4; i++) {
        int ch = tid + i * 256;
        int r = ch >> 3, c = ch & 7;
        gA[i] = (uint32_t)((bm + r) * K + c * 8);
        gB[i] = (uint32_t)((bn + r) * K + c * 8);
        sO[i] = (uint32_t)(r * APITCH + c * 16);
    }

    float acc[4][4][4];
    #pragma unroll
    for (int i = 0; i < 4; i++)
        #pragma unroll
        for (int j = 0; j < 4; j++)
            #pragma unroll
            for (int q = 0; q < 4; q++) acc[i][j][q] = 0.0f;

    const int nIter = K >> 6;

    #pragma unroll
    for (int s = 0; s < 2; s++) {
        const uint32_t k0 = (uint32_t)s << 6;
        #pragma unroll
        for (int i = 0; i < 4; i++) {
            CP_ASYNC16(sA + s * A_STAGE + sO[i], A + gA[i] + k0);
            CP_ASYNC16(sB + s * A_STAGE + sO[i], B + gB[i] + k0);
        }
        CP_COMMIT();
    }

    const int a_r  = lane & 15;
    const int a_c  = (lane >> 4) << 3;
    const int b_m4 = lane >> 3;
    const int b_fnp = b_m4 >> 1;
    const int b_kk  = (b_m4 & 1) << 3;
    const int b_rr  = lane & 7;

    int cur = 0;
    for (int it = 0; it < nIter; it++) {
        if (it + 1 < nIter) { CP_WAIT(1); } else { CP_WAIT(0); }
        __syncthreads();

        if (it + 2 < nIter) {
            const int s2 = (it + 2) % 3;
            const uint32_t k2 = (uint32_t)(it + 2) << 6;
            #pragma unroll
            for (int i = 0; i < 4; i++) {
                CP_ASYNC16(sA + s2 * A_STAGE + sO[i], A + gA[i] + k2);
                CP_ASYNC16(sB + s2 * A_STAGE + sO[i], B + gB[i] + k2);
            }
            CP_COMMIT();
        }

        const uint32_t aBase = sA + cur * A_STAGE;
        const uint32_t bBase = sB + cur * A_STAGE;
        #pragma unroll
        for (int s = 0; s < 4; s++) {
            const int kb = s * 16;
            uint32_t af[4][4];
            uint32_t bfr[2][4];
            #pragma unroll
            for (int fm = 0; fm < 4; fm++) {
                uint32_t ad = aBase + (wm * 64 + fm * 16 + a_r) * APITCH + (kb + a_c) * 2;
                LDSM4(af[fm][0], af[fm][1], af[fm][2], af[fm][3], ad);
            }
            #pragma unroll
            for (int p = 0; p < 2; p++) {
                uint32_t bd = bBase + (wn * 32 + p * 16 + b_fnp * 8 + b_rr) * APITCH + (kb + b_kk) * 2;
                LDSM4(bfr[p][0], bfr[p][1], bfr[p][2], bfr[p][3], bd);
            }
            #pragma unroll
            for (int fm = 0; fm < 4; fm++)
                #pragma unroll
                for (int fn = 0; fn < 4; fn++)
                    mma16816(acc[fm][fn], af[fm], &bfr[fn >> 1][(fn & 1) * 2]);
        }
        cur = (cur + 1) % 3;
    }

    #pragma unroll
    for (int fm = 0; fm < 4; fm++) {
        #pragma unroll
        for (int fn = 0; fn < 4; fn++) {
            size_t r  = bm + wm * 64 + fm * 16 + grp;
            size_t cN = bn + wn * 32 + fn * 8 + tig * 2;
            if (HALF_OUT) {
                __half* C = (__half*)Cv;
                *reinterpret_cast<__half2*>(&C[r * N + cN]) =
                    __floats2half2_rn(acc[fm][fn][0], acc[fm][fn][1]);
                *reinterpret_cast<__half2*>(&C[(r + 8) * N + cN]) =
                    __floats2half2_rn(acc[fm][fn][2], acc[fm][fn][3]);
            } else {
                float* C = (float*)Cv;
                *reinterpret_cast<float2*>(&C[r * N + cN])       = make_float2(acc[fm][fn][0], acc[fm][fn][1]);
                *reinterpret_cast<float2*>(&C[(r + 8) * N + cN]) = make_float2(acc[fm][fn][2], acc[fm][fn][3]);
            }
        }
    }
}

// ---------------- x_proj split-K GEMM: Cp[ks][M][32] = A[M, ks-slice] * B[0:32, ks-slice]^T ----
#define XKS 8
#define XKSL (DINNER / XKS)     // 256
#define XB_STAGE (32 * APITCH)
__global__ __launch_bounds__(256, 2) void gemm_xproj(
    const __half* __restrict__ A, const __half* __restrict__ B, float* __restrict__ Cp)
{
    extern __shared__ char sm[];
    const uint32_t sA = smem_u32(sm);                 // [2][128][APITCH]
    const uint32_t sB = sA + 2 * A_STAGE;             // [2][32][APITCH]

    const int tid  = threadIdx.x;
    const int lane = tid & 31;
    const int wid  = tid >> 5;                        // 8 warps, 16 rows each
    const int grp  = lane >> 2;
    const int tig  = lane & 3;
    const size_t bm = (size_t)blockIdx.y * 128;
    const int ks   = blockIdx.x;
    const int kb0  = ks * XKSL;

    uint32_t gA[4], oA[4];
    #pragma unroll
    for (int i = 0; i < 4; i++) {
        int ch = tid + i * 256;
        int r = ch >> 3, c = ch & 7;
        gA[i] = (uint32_t)((bm + r) * DINNER + kb0 + c * 8);
        oA[i] = (uint32_t)(r * APITCH + c * 16);
    }
    const int rB = tid >> 3, cB = tid & 7;
    const uint32_t gBo = (uint32_t)(rB * DINNER + kb0 + cB * 8);
    const uint32_t oBo = (uint32_t)(rB * APITCH + cB * 16);

    float acc[4][4];
    #pragma unroll
    for (int j = 0; j < 4; j++)
        #pragma unroll
        for (int q = 0; q < 4; q++) acc[j][q] = 0.0f;

    const int nIter = XKSL >> 6;                      // 4

    #pragma unroll
    for (int i = 0; i < 4; i++) CP_ASYNC16(sA + oA[i], A + gA[i]);
    CP_ASYNC16(sB + oBo, B + gBo);
    CP_COMMIT();

    const int a_r  = lane & 15;
    const int a_c  = (lane >> 4) << 3;
    const int b_m4 = lane >> 3;
    const int b_fnp = b_m4 >> 1;
    const int b_kk  = (b_m4 & 1) << 3;
    const int b_rr  = lane & 7;

    for (int it = 0; it < nIter; it++) {
        const int st = it & 1;
        if (it + 1 < nIter) {
            const uint32_t k1 = (uint32_t)(it + 1) << 6;
            #pragma unroll
            for (int i = 0; i < 4; i++)
                CP_ASYNC16(sA + (st ^ 1) * A_STAGE + oA[i], A + gA[i] + k1);
            CP_ASYNC16(sB + (st ^ 1) * XB_STAGE + oBo, B + gBo + k1);
            CP_COMMIT();
            CP_WAIT(1);
        } else {
            CP_WAIT(0);
        }
        __syncthreads();

        const uint32_t aBase = sA + st * A_STAGE;
        const uint32_t bBase = sB + st * XB_STAGE;
        #pragma unroll
        for (int s = 0; s < 4; s++) {
            const int kb = s * 16;
            uint32_t af[4];
            uint32_t bfr[2][4];
            uint32_t ad = aBase + (wid * 16 + a_r) * APITCH + (kb + a_c) * 2;
            LDSM4(af[0], af[1], af[2], af[3], ad);
            #pragma unroll
            for (int p = 0; p < 2; p++) {
                uint32_t bd = bBase + (p * 16 + b_fnp * 8 + b_rr) * APITCH + (kb + b_kk) * 2;
                LDSM4(bfr[p][0], bfr[p][1], bfr[p][2], bfr[p][3], bd);
            }
            #pragma unroll
            for (int fn = 0; fn < 4; fn++)
                mma16816(acc[fn], af, &bfr[fn >> 1][(fn & 1) * 2]);
        }
        __syncthreads();
    }

    float* Co = Cp + (size_t)ks * NTOK * 32;
    #pragma unroll
    for (int fn = 0; fn < 4; fn++) {
        size_t r = bm + wid * 16 + grp;
        int   c  = fn * 8 + tig * 2;
        *reinterpret_cast<float2*>(&Co[r * 32 + c])       = make_float2(acc[fn][0], acc[fn][1]);
        *reinterpret_cast<float2*>(&Co[(r + 8) * 32 + c]) = make_float2(acc[fn][2], acc[fn][3]);
    }
}

// sum the 8 split-K partials -> g_bc
__global__ void reduce_bc_kernel(const float* __restrict__ Cp, float* __restrict__ bc)
{
    const int n4 = NTOK * 32 / 4;
    int i = blockIdx.x * blockDim.x + threadIdx.x;
    if (i >= n4) return;
    const float4* p = reinterpret_cast<const float4*>(Cp);
    float4 o = p[i];
    #pragma unroll
    for (int k = 1; k < XKS; k++) {
        float4 v = p[i + (size_t)k * n4];
        o.x += v.x; o.y += v.y; o.z += v.z; o.w += v.w;
    }
    reinterpret_cast<float4*>(bc)[i] = o;
}

// ---------------- depthwise causal conv1d (k=4) + silu ----------------
// 4 tokens x 4 channels per thread: 7 row-reads for 16 outputs.
__global__ void conv_silu_kernel(const __half* __restrict__ xz, const float* __restrict__ cw,
                                 const float* __restrict__ cb, __half* __restrict__ xs1)
{
    int i = blockIdx.x * blockDim.x + threadIdx.x;       // [tok-group(4)][chan-group(4)]
    if (i >= (NTOK / 4) * (DINNER / 4)) return;
    const int tg  = i >> 9;                              // token group (0..1023)
    const int d4  = (i & 511) << 2;                      // channel base
    const int tok0 = tg << 2;                            // first token of group
    const int l0   = tok0 & (LL - 1);                    // position in sequence

    float4 bias = *reinterpret_cast<const float4*>(cb + d4);
    const float4* cwv = reinterpret_cast<const float4*>(cw + d4 * 4);
    float4 w0 = cwv[0], w1 = cwv[1], w2 = cwv[2], w3 = cwv[3];
    const float* wp[4] = { reinterpret_cast<const float*>(&w0), reinterpret_cast<const float*>(&w1),
                           reinterpret_cast<const float*>(&w2), reinterpret_cast<const float*>(&w3) };

    float v[7][4];
    #pragma unroll
    for (int r = 0; r < 7; r++) {
        int lt = l0 - 3 + r;
        if (lt >= 0) {
            uint2 u = *reinterpret_cast<const uint2*>(xz + (size_t)(tok0 - 3 + r) * 4096 + d4);
            float2 a = __half22float2(*reinterpret_cast<const __half2*>(&u.x));
            float2 b = __half22float2(*reinterpret_cast<const __half2*>(&u.y));
            v[r][0] = a.x; v[r][1] = a.y; v[r][2] = b.x; v[r][3] = b.y;
        } else {
            v[r][0] = v[r][1] = v[r][2] = v[r][3] = 0.0f;
        }
    }

    #pragma unroll
    for (int t = 0; t < 4; t++) {
        float o[4];
        #pragma unroll
        for (int c = 0; c < 4; c++) {
            float acc = reinterpret_cast<const float*>(&bias)[c];
            #pragma unroll
            for (int k = 0; k < 4; k++)
                acc = fmaf(wp[c][k], v[t + k][c], acc);
            o[c] = acc / (1.0f + __expf(-acc));
        }
        __half2 h01 = __floats2half2_rn(o[0], o[1]);
        __half2 h23 = __floats2half2_rn(o[2], o[3]);
        uint2 u;
        u.x = *reinterpret_cast<const unsigned*>(&h01);
        u.y = *reinterpret_cast<const unsigned*>(&h23);
        *reinterpret_cast<uint2*>(xs1 + (size_t)(tok0 + t) * DINNER + d4) = u;
    }
}

// ---------------- chunked SSM scan + D skip + silu(z) gate, fp16 in/out ----------------
// dA = exp(-0.1*n) <= 0.905 -> truncation after 128 steps < 3e-5 of steady state.
// 16 chunks of 128 steps, 128-step warm-up. 512 CTAs x 128 thr.
#define SCHUNK 128
#define SWARM  128
__global__ __launch_bounds__(128) void scan_kernel(
    const __half* __restrict__ xs1, const __half* __restrict__ xz,
    const float* __restrict__ bc, const float* __restrict__ A_log,
    const float* __restrict__ Dparam, __half* __restrict__ y1)
{
    __shared__ float BCs[4][8][32];
    const int tid  = threadIdx.x;
    const int wid  = tid >> 5;
    const int lane = tid & 31;
    const int b     = blockIdx.x >> 8;
    const int rem   = blockIdx.x & 255;
    const int dblk  = rem >> 4;
    const int chunk = rem & 15;
    const int d = dblk * 128 + wid * 32 + lane;

    const int w0 = chunk * SCHUNK;
    const int t0 = chunk ? (w0 - SWARM) : 0;
    const int t1 = w0 + SCHUNK;

    unsigned long long dAP[8], hP[8];
    #pragma unroll
    for (int i = 0; i < 8; i++) {
        float a0 = __expf(-0.1f * __expf(A_log[d * 16 + 2 * i]));
        float a1 = __expf(-0.1f * __expf(A_log[d * 16 + 2 * i + 1]));
        asm("mov.b64 %0, {%1,%2};" : "=l"(dAP[i]) : "f"(a0), "f"(a1));
        hP[i] = 0ull;
    }
    const float Dv = Dparam[d];
    const float* bcb = bc + (size_t)b * LL * 32;
    float (*ring)[32] = BCs[wid];

    #pragma unroll
    for (int s = 0; s < 3; s++) {
        CP_ASYNC8(smem_u32(&ring[(t0 + 2 * s) & 7][0]) + lane * 8,
                  bcb + (size_t)(t0 + 2 * s) * 32 + lane * 2);
        CP_COMMIT();
    }

    const __half* xsp = xs1 + (size_t)b * LL * DINNER + d;
    const __half* zp  = xz  + (size_t)b * LL * 4096 + DINNER + d;
    __half* y1p = y1 + (size_t)b * LL * DINNER + d;

    float xv[4], zv[4];
    #pragma unroll
    for (int i = 0; i < 4; i++) {
        xv[i] = __half2float(__ldg(xsp + (size_t)(t0 + i) * DINNER));
        zv[i] = __half2float(__ldg(zp  + (size_t)(t0 + i) * 4096));
    }

    for (int t = t0; t < t1; t++) {
        if (!(t & 1)) {
            if (t + 6 < t1)
                CP_ASYNC8(smem_u32(&ring[(t + 6) & 7][0]) + lane * 8,
                          bcb + (size_t)(t + 6) * 32 + lane * 2);
            CP_COMMIT();
        }
        CP_WAIT(3);
        __syncwarp();

        const int rs = t & 3;
        const float xvc = xv[rs], zvc = zv[rs];
        if (t + 4 < t1) {
            xv[rs] = __half2float(__ldg(xsp + (size_t)(t + 4) * DINNER));
            zv[rs] = __half2float(__ldg(zp  + (size_t)(t + 4) * 4096));
        }

        const float s = 0.1f * xvc;
        unsigned long long sP;
        asm("mov.b64 %0, {%1,%2};" : "=l"(sP) : "f"(s), "f"(s));

        const int slot = t & 7;
        unsigned long long yP[4] = {0ull, 0ull, 0ull, 0ull};
        #pragma unroll
        for (int i = 0; i < 8; i++) {
            unsigned long long bP = *reinterpret_cast<const unsigned long long*>(&ring[slot][2 * i]);
            unsigned long long cP = *reinterpret_cast<const unsigned long long*>(&ring[slot][16 + 2 * i]);
            unsigned long long tP;
            asm("mul.rn.f32x2 %0, %1, %2;" : "=l"(tP) : "l"(sP), "l"(bP));
            asm("fma.rn.f32x2 %0, %1, %2, %3;" : "=l"(hP[i]) : "l"(dAP[i]), "l"(hP[i]), "l"(tP));
            asm("fma.rn.f32x2 %0, %1, %2, %3;" : "=l"(yP[i & 3]) : "l"(hP[i]), "l"(cP), "l"(yP[i & 3]));
        }

        if (t >= w0) {
            float y = 0.0f;
            #pragma unroll
            for (int i = 0; i < 4; i++) {
                float lo, hi;
                asm("mov.b64 {%0,%1}, %2;" : "=f"(lo), "=f"(hi) : "l"(yP[i]));
                y += lo + hi;
            }
            float sg = 1.0f / (1.0f + __expf(-zvc));
            float yv = fmaf(xvc, Dv, y) * (zvc * sg);
            y1p[(size_t)t * DINNER] = __float2half(yv);
        }
    }
}

// ---------------- launch ----------------
extern "C" void kernel_launch(void* const* d_in, const int* in_sizes, int n_in,
                              void* d_out, int out_size)
{
    (void)in_sizes; (void)n_in; (void)out_size;
    const float* x      = (const float*)d_in[0];
    const float* in_w   = (const float*)d_in[1];
    const float* conv_w = (const float*)d_in[2];
    const float* conv_b = (const float*)d_in[3];
    const float* xp_w   = (const float*)d_in[4];
    const float* A_log  = (const float*)d_in[5];
    const float* Dp     = (const float*)d_in[6];
    const float* out_w  = (const float*)d_in[7];

    void *p_xz, *p_bc, *p_bcp, *p_x1, *p_win1, *p_wxp1, *p_wout1, *p_xs1, *p_y1;
    cudaGetSymbolAddress(&p_xz,    g_xz);
    cudaGetSymbolAddress(&p_bc,    g_bc);
    cudaGetSymbolAddress(&p_bcp,   g_bcp);
    cudaGetSymbolAddress(&p_x1,    g_x1);
    cudaGetSymbolAddress(&p_win1,  g_win1);
    cudaGetSymbolAddress(&p_wxp1,  g_wxp1);
    cudaGetSymbolAddress(&p_wout1, g_wout1);
    cudaGetSymbolAddress(&p_xs1,   g_xs1);
    cudaGetSymbolAddress(&p_y1,    g_y1);

    const int SMEMG  = 6 * A_STAGE;                       // 110592 (t128, occ 2)
    const int SMEMXP = 2 * A_STAGE + 2 * XB_STAGE;        // 46080
    static int smem_set = 0;
    if (!smem_set) {
        cudaFuncSetAttribute(gemm_t128<1>, cudaFuncAttributeMaxDynamicSharedMemorySize, SMEMG);
        cudaFuncSetAttribute(gemm_t128<0>, cudaFuncAttributeMaxDynamicSharedMemorySize, SMEMG);
        cudaFuncSetAttribute(gemm_xproj,   cudaFuncAttributeMaxDynamicSharedMemorySize, SMEMXP);
        smem_set = 1;
    }

    const int T = 256;

    // all fp16 conversions in one launch
    cvt_all_kernel<<<(CVT_S3 + T - 1) / T, T>>>(x, in_w, xp_w, out_w,
                                                (__half*)p_x1, (__half*)p_win1,
                                                (__half*)p_wxp1, (__half*)p_wout1);

    // in_proj: [4096,1024] x [4096,1024]^T -> xz [4096,4096] (fp16 out, proven t128)
    gemm_t128<1><<<dim3(4096 / 128, NTOK / 128), 256, SMEMG>>>(
        (const __half*)p_x1, (const __half*)p_win1, p_xz,
        NTOK, 4096, DMODEL);

    // depthwise causal conv + silu (4 tokens x 4 channels per thread)
    conv_silu_kernel<<<((NTOK / 4) * (DINNER / 4)) / 256, 256>>>(
        (const __half*)p_xz, conv_w, conv_b, (__half*)p_xs1);

    // x_proj: split-K=8, N=32 tile -> partials, then reduce
    gemm_xproj<<<dim3(XKS, NTOK / 128), 256, SMEMXP>>>(
        (const __half*)p_xs1, (const __half*)p_wxp1, (float*)p_bcp);
    reduce_bc_kernel<<<(NTOK * 32 / 4 + T - 1) / T, T>>>((const float*)p_bcp, (float*)p_bc);

    // chunked SSM scan fused with D skip, silu(z) gate (fp16 xs/z inputs)
    scan_kernel<<<512, 128>>>((const __half*)p_xs1, (const __half*)p_xz, (const float*)p_bc,
                              A_log, Dp, (__half*)p_y1);

    // out_proj: [4096,2048] x [1024,2048]^T -> out [4096,1024] (fp32 output)
    gemm_t128<0><<<dim3(1024 / 128, NTOK / 128), 256, SMEMG>>>(
        (const __half*)p_y1, (const __half*)p_wout1, d_out,
        NTOK, 1024, DINNER);
}

// round 17
// speedup vs baseline: 1.1072x; 1.0502x over previous
#include <cuda_runtime.h>
#include <cuda_fp16.h>
#include <cstdint>

// ---------------- problem constants ----------------
#define BB      2
#define LL      2048
#define DMODEL  1024
#define DINNER  2048
#define NSTATE  16
#define NTOK    (BB*LL)      // 4096 tokens

// ---------------- device scratch (allocation-free rule: __device__ globals) ----------------
__device__ __half  g_xz  [(size_t)NTOK * 4096];         // in_proj output, fp16 [tok][4096] (xs|z)
__device__ float   g_bc  [(size_t)NTOK * 32];           // x_proj output (cols 0..15 B, 16..31 C)
__device__ float   g_bcp [(size_t)8 * NTOK * 32];       // x_proj split-K partials
__device__ __half  g_x1   [(size_t)NTOK * DMODEL];      // fp16 x
__device__ __half  g_win1 [(size_t)4096 * DMODEL];      // fp16 in_proj_w
__device__ __half  g_wxp1 [(size_t)128  * DINNER];      // fp16 x_proj_w (rows 0..31 used)
__device__ __half  g_wout1[(size_t)1024 * DINNER];      // fp16 out_proj_w
__device__ __half  g_xs1  [(size_t)NTOK * DINNER];      // fp16 xs (conv output; feeds xproj AND scan)
__device__ __half  g_y1   [(size_t)NTOK * DINNER];      // fp16 final y (written by scan)

// ---------------- asm helpers ----------------
#define CP_ASYNC16(dst, src) \
    asm volatile("cp.async.cg.shared.global [%0], [%1], 16;\n" :: "r"(dst), "l"(src))
#define CP_ASYNC8(dst, src) \
    asm volatile("cp.async.ca.shared.global [%0], [%1], 8;\n" :: "r"(dst), "l"(src))
#define CP_COMMIT() asm volatile("cp.async.commit_group;\n")
#define CP_WAIT(n)  asm volatile("cp.async.wait_group %0;\n" :: "n"(n))
#define LDSM4(r0, r1, r2, r3, addr) \
    asm volatile("ldmatrix.sync.aligned.m8n8.x4.shared.b16 {%0,%1,%2,%3}, [%4];" \
                 : "=r"(r0), "=r"(r1), "=r"(r2), "=r"(r3) : "r"(addr))

__device__ __forceinline__ uint32_t smem_u32(const void* p)
{
    return (uint32_t)__cvta_generic_to_shared(p);
}

// ---------------- fused fp32 -> fp16 conversion of all operands (one launch) ----------------
#define CVT_S0 (NTOK * DMODEL / 2)
#define CVT_S1 (CVT_S0 + 4096 * DMODEL / 2)
#define CVT_S2 (CVT_S1 + 32 * DINNER / 2)
#define CVT_S3 (CVT_S2 + 1024 * DINNER / 2)

__global__ void cvt_all_kernel(const float* __restrict__ x, const float* __restrict__ in_w,
                               const float* __restrict__ xp_w, const float* __restrict__ out_w,
                               __half* __restrict__ x1, __half* __restrict__ win1,
                               __half* __restrict__ wxp1, __half* __restrict__ wout1)
{
    int i = blockIdx.x * blockDim.x + threadIdx.x;
    if (i >= CVT_S3) return;
    const float* src;
    __half2* dst;
    if (i < CVT_S0)      { src = x;     dst = (__half2*)x1;    /* i */ }
    else if (i < CVT_S1) { src = in_w;  dst = (__half2*)win1;  i -= CVT_S0; }
    else if (i < CVT_S2) { src = xp_w;  dst = (__half2*)wxp1;  i -= CVT_S1; }
    else                 { src = out_w; dst = (__half2*)wout1; i -= CVT_S2; }
    float2 v = reinterpret_cast<const float2*>(src)[i];
    dst[i] = __floats2half2_rn(v.x, v.y);
}

// ---------------- fp16 mma helpers ----------------
__device__ __forceinline__ void mma16816(float* c, const uint32_t* a, const uint32_t* b)
{
    asm volatile(
        "mma.sync.aligned.m16n8k16.row.col.f32.f16.f16.f32 "
        "{%0,%1,%2,%3}, {%4,%5,%6,%7}, {%8,%9}, {%0,%1,%2,%3};"
        : "+f"(c[0]), "+f"(c[1]), "+f"(c[2]), "+f"(c[3])
        : "r"(a[0]), "r"(a[1]), "r"(a[2]), "r"(a[3]), "r"(b[0]), "r"(b[1]));
}

#define APITCH 144               // bytes per 64-half row (64 + 8 pad), 16B-aligned
#define A_STAGE  (128 * APITCH)  // 18432 B (128-row tile)

// ---------------- GEMM 128x128 tile, BK=64, 3-stage cp.async, occupancy 2 ----------------
// C[M, bn-range] = A[M,K] * B[N,K]^T. ldN is the C row stride (elements).
// grid.x may cover a sub-range of columns of a wider C (B pre-offset by caller).
// HALF_OUT=1: C is __half*, else float*.  (FROZEN inner loop: R9/R15 experiments)
template<int HALF_OUT>
__global__ __launch_bounds__(256, 2) void gemm_t128(
    const __half* __restrict__ A, const __half* __restrict__ B,
    void* __restrict__ Cv, int M, int ldN, int K)
{
    extern __shared__ char sm[];
    const uint32_t sA = smem_u32(sm);                 // 3 stages A
    const uint32_t sB = sA + 3 * A_STAGE;             // 3 stages B

    const int tid  = threadIdx.x;
    const int lane = tid & 31;
    const int wid  = tid >> 5;
    const int wm   = wid & 1;        // 2 warps along M (64 each)
    const int wn   = wid >> 1;       // 4 warps along N (32 each)
    const int grp  = lane >> 2;
    const int tig  = lane & 3;
    const size_t bm = (size_t)blockIdx.y * 128;
    const size_t bn = (size_t)blockIdx.x * 128;

    uint32_t gA[4], gB[4], sO[4];
    #pragma unroll
    for (int i = 0; i < 4; i++) {
        int ch = tid + i * 256;
        int r = ch >> 3, c = ch & 7;
        gA[i] = (uint32_t)((bm + r) * K + c * 8);
        gB[i] = (uint32_t)((bn + r) * K + c * 8);
        sO[i] = (uint32_t)(r * APITCH + c * 16);
    }

    float acc[4][4][4];
    #pragma unroll
    for (int i = 0; i < 4; i++)
        #pragma unroll
        for (int j = 0; j < 4; j++)
            #pragma unroll
            for (int q = 0; q < 4; q++) acc[i][j][q] = 0.0f;

    const int nIter = K >> 6;

    #pragma unroll
    for (int s = 0; s < 2; s++) {
        const uint32_t k0 = (uint32_t)s << 6;
        #pragma unroll
        for (int i = 0; i < 4; i++) {
            CP_ASYNC16(sA + s * A_STAGE + sO[i], A + gA[i] + k0);
            CP_ASYNC16(sB + s * A_STAGE + sO[i], B + gB[i] + k0);
        }
        CP_COMMIT();
    }

    const int a_r  = lane & 15;
    const int a_c  = (lane >> 4) << 3;
    const int b_m4 = lane >> 3;
    const int b_fnp = b_m4 >> 1;
    const int b_kk  = (b_m4 & 1) << 3;
    const int b_rr  = lane & 7;

    int cur = 0;
    for (int it = 0; it < nIter; it++) {
        if (it + 1 < nIter) { CP_WAIT(1); } else { CP_WAIT(0); }
        __syncthreads();

        if (it + 2 < nIter) {
            const int s2 = (it + 2) % 3;
            const uint32_t k2 = (uint32_t)(it + 2) << 6;
            #pragma unroll
            for (int i = 0; i < 4; i++) {
                CP_ASYNC16(sA + s2 * A_STAGE + sO[i], A + gA[i] + k2);
                CP_ASYNC16(sB + s2 * A_STAGE + sO[i], B + gB[i] + k2);
            }
            CP_COMMIT();
        }

        const uint32_t aBase = sA + cur * A_STAGE;
        const uint32_t bBase = sB + cur * A_STAGE;
        #pragma unroll
        for (int s = 0; s < 4; s++) {
            const int kb = s * 16;
            uint32_t af[4][4];
            uint32_t bfr[2][4];
            #pragma unroll
            for (int fm = 0; fm < 4; fm++) {
                uint32_t ad = aBase + (wm * 64 + fm * 16 + a_r) * APITCH + (kb + a_c) * 2;
                LDSM4(af[fm][0], af[fm][1], af[fm][2], af[fm][3], ad);
            }
            #pragma unroll
            for (int p = 0; p < 2; p++) {
                uint32_t bd = bBase + (wn * 32 + p * 16 + b_fnp * 8 + b_rr) * APITCH + (kb + b_kk) * 2;
                LDSM4(bfr[p][0], bfr[p][1], bfr[p][2], bfr[p][3], bd);
            }
            #pragma unroll
            for (int fm = 0; fm < 4; fm++)
                #pragma unroll
                for (int fn = 0; fn < 4; fn++)
                    mma16816(acc[fm][fn], af[fm], &bfr[fn >> 1][(fn & 1) * 2]);
        }
        cur = (cur + 1) % 3;
    }

    #pragma unroll
    for (int fm = 0; fm < 4; fm++) {
        #pragma unroll
        for (int fn = 0; fn < 4; fn++) {
            size_t r  = bm + wm * 64 + fm * 16 + grp;
            size_t cN = bn + wn * 32 + fn * 8 + tig * 2;
            if (HALF_OUT) {
                __half* C = (__half*)Cv;
                *reinterpret_cast<__half2*>(&C[r * ldN + cN]) =
                    __floats2half2_rn(acc[fm][fn][0], acc[fm][fn][1]);
                *reinterpret_cast<__half2*>(&C[(r + 8) * ldN + cN]) =
                    __floats2half2_rn(acc[fm][fn][2], acc[fm][fn][3]);
            } else {
                float* C = (float*)Cv;
                *reinterpret_cast<float2*>(&C[r * ldN + cN])       = make_float2(acc[fm][fn][0], acc[fm][fn][1]);
                *reinterpret_cast<float2*>(&C[(r + 8) * ldN + cN]) = make_float2(acc[fm][fn][2], acc[fm][fn][3]);
            }
        }
    }
}

// ---------------- x_proj split-K GEMM: Cp[ks][M][32] = A[M, ks-slice] * B[0:32, ks-slice]^T ----
#define XKS 8
#define XKSL (DINNER / XKS)     // 256
#define XB_STAGE (32 * APITCH)
__global__ __launch_bounds__(256, 2) void gemm_xproj(
    const __half* __restrict__ A, const __half* __restrict__ B, float* __restrict__ Cp)
{
    extern __shared__ char sm[];
    const uint32_t sA = smem_u32(sm);                 // [2][128][APITCH]
    const uint32_t sB = sA + 2 * A_STAGE;             // [2][32][APITCH]

    const int tid  = threadIdx.x;
    const int lane = tid & 31;
    const int wid  = tid >> 5;                        // 8 warps, 16 rows each
    const int grp  = lane >> 2;
    const int tig  = lane & 3;
    const size_t bm = (size_t)blockIdx.y * 128;
    const int ks   = blockIdx.x;
    const int kb0  = ks * XKSL;

    uint32_t gA[4], oA[4];
    #pragma unroll
    for (int i = 0; i < 4; i++) {
        int ch = tid + i * 256;
        int r = ch >> 3, c = ch & 7;
        gA[i] = (uint32_t)((bm + r) * DINNER + kb0 + c * 8);
        oA[i] = (uint32_t)(r * APITCH + c * 16);
    }
    const int rB = tid >> 3, cB = tid & 7;
    const uint32_t gBo = (uint32_t)(rB * DINNER + kb0 + cB * 8);
    const uint32_t oBo = (uint32_t)(rB * APITCH + cB * 16);

    float acc[4][4];
    #pragma unroll
    for (int j = 0; j < 4; j++)
        #pragma unroll
        for (int q = 0; q < 4; q++) acc[j][q] = 0.0f;

    const int nIter = XKSL >> 6;                      // 4

    #pragma unroll
    for (int i = 0; i < 4; i++) CP_ASYNC16(sA + oA[i], A + gA[i]);
    CP_ASYNC16(sB + oBo, B + gBo);
    CP_COMMIT();

    const int a_r  = lane & 15;
    const int a_c  = (lane >> 4) << 3;
    const int b_m4 = lane >> 3;
    const int b_fnp = b_m4 >> 1;
    const int b_kk  = (b_m4 & 1) << 3;
    const int b_rr  = lane & 7;

    for (int it = 0; it < nIter; it++) {
        const int st = it & 1;
        if (it + 1 < nIter) {
            const uint32_t k1 = (uint32_t)(it + 1) << 6;
            #pragma unroll
            for (int i = 0; i < 4; i++)
                CP_ASYNC16(sA + (st ^ 1) * A_STAGE + oA[i], A + gA[i] + k1);
            CP_ASYNC16(sB + (st ^ 1) * XB_STAGE + oBo, B + gBo + k1);
            CP_COMMIT();
            CP_WAIT(1);
        } else {
            CP_WAIT(0);
        }
        __syncthreads();

        const uint32_t aBase = sA + st * A_STAGE;
        const uint32_t bBase = sB + st * XB_STAGE;
        #pragma unroll
        for (int s = 0; s < 4; s++) {
            const int kb = s * 16;
            uint32_t af[4];
            uint32_t bfr[2][4];
            uint32_t ad = aBase + (wid * 16 + a_r) * APITCH + (kb + a_c) * 2;
            LDSM4(af[0], af[1], af[2], af[3], ad);
            #pragma unroll
            for (int p = 0; p < 2; p++) {
                uint32_t bd = bBase + (p * 16 + b_fnp * 8 + b_rr) * APITCH + (kb + b_kk) * 2;
                LDSM4(bfr[p][0], bfr[p][1], bfr[p][2], bfr[p][3], bd);
            }
            #pragma unroll
            for (int fn = 0; fn < 4; fn++)
                mma16816(acc[fn], af, &bfr[fn >> 1][(fn & 1) * 2]);
        }
        __syncthreads();
    }

    float* Co = Cp + (size_t)ks * NTOK * 32;
    #pragma unroll
    for (int fn = 0; fn < 4; fn++) {
        size_t r = bm + wid * 16 + grp;
        int   c  = fn * 8 + tig * 2;
        *reinterpret_cast<float2*>(&Co[r * 32 + c])       = make_float2(acc[fn][0], acc[fn][1]);
        *reinterpret_cast<float2*>(&Co[(r + 8) * 32 + c]) = make_float2(acc[fn][2], acc[fn][3]);
    }
}

// sum the 8 split-K partials -> g_bc
__global__ void reduce_bc_kernel(const float* __restrict__ Cp, float* __restrict__ bc)
{
    const int n4 = NTOK * 32 / 4;
    int i = blockIdx.x * blockDim.x + threadIdx.x;
    if (i >= n4) return;
    const float4* p = reinterpret_cast<const float4*>(Cp);
    float4 o = p[i];
    #pragma unroll
    for (int k = 1; k < XKS; k++) {
        float4 v = p[i + (size_t)k * n4];
        o.x += v.x; o.y += v.y; o.z += v.z; o.w += v.w;
    }
    reinterpret_cast<float4*>(bc)[i] = o;
}

// ---------------- depthwise causal conv1d (k=4) + silu ----------------
// 4 tokens x 4 channels per thread: 7 row-reads for 16 outputs.
__global__ void conv_silu_kernel(const __half* __restrict__ xz, const float* __restrict__ cw,
                                 const float* __restrict__ cb, __half* __restrict__ xs1)
{
    int i = blockIdx.x * blockDim.x + threadIdx.x;       // [tok-group(4)][chan-group(4)]
    if (i >= (NTOK / 4) * (DINNER / 4)) return;
    const int tg  = i >> 9;                              // token group (0..1023)
    const int d4  = (i & 511) << 2;                      // channel base
    const int tok0 = tg << 2;                            // first token of group
    const int l0   = tok0 & (LL - 1);                    // position in sequence

    float4 bias = *reinterpret_cast<const float4*>(cb + d4);
    const float4* cwv = reinterpret_cast<const float4*>(cw + d4 * 4);
    float4 w0 = cwv[0], w1 = cwv[1], w2 = cwv[2], w3 = cwv[3];
    const float* wp[4] = { reinterpret_cast<const float*>(&w0), reinterpret_cast<const float*>(&w1),
                           reinterpret_cast<const float*>(&w2), reinterpret_cast<const float*>(&w3) };

    float v[7][4];
    #pragma unroll
    for (int r = 0; r < 7; r++) {
        int lt = l0 - 3 + r;
        if (lt >= 0) {
            uint2 u = *reinterpret_cast<const uint2*>(xz + (size_t)(tok0 - 3 + r) * 4096 + d4);
            float2 a = __half22float2(*reinterpret_cast<const __half2*>(&u.x));
            float2 b = __half22float2(*reinterpret_cast<const __half2*>(&u.y));
            v[r][0] = a.x; v[r][1] = a.y; v[r][2] = b.x; v[r][3] = b.y;
        } else {
            v[r][0] = v[r][1] = v[r][2] = v[r][3] = 0.0f;
        }
    }

    #pragma unroll
    for (int t = 0; t < 4; t++) {
        float o[4];
        #pragma unroll
        for (int c = 0; c < 4; c++) {
            float acc = reinterpret_cast<const float*>(&bias)[c];
            #pragma unroll
            for (int k = 0; k < 4; k++)
                acc = fmaf(wp[c][k], v[t + k][c], acc);
            o[c] = acc / (1.0f + __expf(-acc));
        }
        __half2 h01 = __floats2half2_rn(o[0], o[1]);
        __half2 h23 = __floats2half2_rn(o[2], o[3]);
        uint2 u;
        u.x = *reinterpret_cast<const unsigned*>(&h01);
        u.y = *reinterpret_cast<const unsigned*>(&h23);
        *reinterpret_cast<uint2*>(xs1 + (size_t)(tok0 + t) * DINNER + d4) = u;
    }
}

// ---------------- chunked SSM scan + D skip + silu(z) gate, fp16 in/out ----------------
// dA = exp(-0.1*n) <= 0.905 -> truncation after 128 steps < 3e-5 of steady state.
// 16 chunks of 128 steps, 128-step warm-up. 512 CTAs x 128 thr.
#define SCHUNK 128
#define SWARM  128
__global__ __launch_bounds__(128) void scan_kernel(
    const __half* __restrict__ xs1, const __half* __restrict__ xz,
    const float* __restrict__ bc, const float* __restrict__ A_log,
    const float* __restrict__ Dparam, __half* __restrict__ y1)
{
    __shared__ float BCs[4][8][32];
    const int tid  = threadIdx.x;
    const int wid  = tid >> 5;
    const int lane = tid & 31;
    const int b     = blockIdx.x >> 8;
    const int rem   = blockIdx.x & 255;
    const int dblk  = rem >> 4;
    const int chunk = rem & 15;
    const int d = dblk * 128 + wid * 32 + lane;

    const int w0 = chunk * SCHUNK;
    const int t0 = chunk ? (w0 - SWARM) : 0;
    const int t1 = w0 + SCHUNK;

    unsigned long long dAP[8], hP[8];
    #pragma unroll
    for (int i = 0; i < 8; i++) {
        float a0 = __expf(-0.1f * __expf(A_log[d * 16 + 2 * i]));
        float a1 = __expf(-0.1f * __expf(A_log[d * 16 + 2 * i + 1]));
        asm("mov.b64 %0, {%1,%2};" : "=l"(dAP[i]) : "f"(a0), "f"(a1));
        hP[i] = 0ull;
    }
    const float Dv = Dparam[d];
    const float* bcb = bc + (size_t)b * LL * 32;
    float (*ring)[32] = BCs[wid];

    #pragma unroll
    for (int s = 0; s < 3; s++) {
        CP_ASYNC8(smem_u32(&ring[(t0 + 2 * s) & 7][0]) + lane * 8,
                  bcb + (size_t)(t0 + 2 * s) * 32 + lane * 2);
        CP_COMMIT();
    }

    const __half* xsp = xs1 + (size_t)b * LL * DINNER + d;
    const __half* zp  = xz  + (size_t)b * LL * 4096 + DINNER + d;
    __half* y1p = y1 + (size_t)b * LL * DINNER + d;

    float xv[4], zv[4];
    #pragma unroll
    for (int i = 0; i < 4; i++) {
        xv[i] = __half2float(__ldg(xsp + (size_t)(t0 + i) * DINNER));
        zv[i] = __half2float(__ldg(zp  + (size_t)(t0 + i) * 4096));
    }

    for (int t = t0; t < t1; t++) {
        if (!(t & 1)) {
            if (t + 6 < t1)
                CP_ASYNC8(smem_u32(&ring[(t + 6) & 7][0]) + lane * 8,
                          bcb + (size_t)(t + 6) * 32 + lane * 2);
            CP_COMMIT();
        }
        CP_WAIT(3);
        __syncwarp();

        const int rs = t & 3;
        const float xvc = xv[rs], zvc = zv[rs];
        if (t + 4 < t1) {
            xv[rs] = __half2float(__ldg(xsp + (size_t)(t + 4) * DINNER));
            zv[rs] = __half2float(__ldg(zp  + (size_t)(t + 4) * 4096));
        }

        const float s = 0.1f * xvc;
        unsigned long long sP;
        asm("mov.b64 %0, {%1,%2};" : "=l"(sP) : "f"(s), "f"(s));

        const int slot = t & 7;
        unsigned long long yP[4] = {0ull, 0ull, 0ull, 0ull};
        #pragma unroll
        for (int i = 0; i < 8; i++) {
            unsigned long long bP = *reinterpret_cast<const unsigned long long*>(&ring[slot][2 * i]);
            unsigned long long cP = *reinterpret_cast<const unsigned long long*>(&ring[slot][16 + 2 * i]);
            unsigned long long tP;
            asm("mul.rn.f32x2 %0, %1, %2;" : "=l"(tP) : "l"(sP), "l"(bP));
            asm("fma.rn.f32x2 %0, %1, %2, %3;" : "=l"(hP[i]) : "l"(dAP[i]), "l"(hP[i]), "l"(tP));
            asm("fma.rn.f32x2 %0, %1, %2, %3;" : "=l"(yP[i & 3]) : "l"(hP[i]), "l"(cP), "l"(yP[i & 3]));
        }

        if (t >= w0) {
            float y = 0.0f;
            #pragma unroll
            for (int i = 0; i < 4; i++) {
                float lo, hi;
                asm("mov.b64 {%0,%1}, %2;" : "=f"(lo), "=f"(hi) : "l"(yP[i]));
                y += lo + hi;
            }
            float sg = 1.0f / (1.0f + __expf(-zvc));
            float yv = fmaf(xvc, Dv, y) * (zvc * sg);
            y1p[(size_t)t * DINNER] = __float2half(yv);
        }
    }
}

// ---------------- launch ----------------
extern "C" void kernel_launch(void* const* d_in, const int* in_sizes, int n_in,
                              void* d_out, int out_size)
{
    (void)in_sizes; (void)n_in; (void)out_size;
    const float* x      = (const float*)d_in[0];
    const float* in_w   = (const float*)d_in[1];
    const float* conv_w = (const float*)d_in[2];
    const float* conv_b = (const float*)d_in[3];
    const float* xp_w   = (const float*)d_in[4];
    const float* A_log  = (const float*)d_in[5];
    const float* Dp     = (const float*)d_in[6];
    const float* out_w  = (const float*)d_in[7];

    void *p_xz, *p_bc, *p_bcp, *p_x1, *p_win1, *p_wxp1, *p_wout1, *p_xs1, *p_y1;
    cudaGetSymbolAddress(&p_xz,    g_xz);
    cudaGetSymbolAddress(&p_bc,    g_bc);
    cudaGetSymbolAddress(&p_bcp,   g_bcp);
    cudaGetSymbolAddress(&p_x1,    g_x1);
    cudaGetSymbolAddress(&p_win1,  g_win1);
    cudaGetSymbolAddress(&p_wxp1,  g_wxp1);
    cudaGetSymbolAddress(&p_wout1, g_wout1);
    cudaGetSymbolAddress(&p_xs1,   g_xs1);
    cudaGetSymbolAddress(&p_y1,    g_y1);

    const int SMEMG  = 6 * A_STAGE;                       // 110592 (t128, occ 2)
    const int SMEMXP = 2 * A_STAGE + 2 * XB_STAGE;        // 46080

    static cudaStream_t s2 = nullptr;
    static cudaEvent_t  e_fork = nullptr, e_join = nullptr;
    static int init_done = 0;
    if (!init_done) {
        cudaFuncSetAttribute(gemm_t128<1>, cudaFuncAttributeMaxDynamicSharedMemorySize, SMEMG);
        cudaFuncSetAttribute(gemm_t128<0>, cudaFuncAttributeMaxDynamicSharedMemorySize, SMEMG);
        cudaFuncSetAttribute(gemm_xproj,   cudaFuncAttributeMaxDynamicSharedMemorySize, SMEMXP);
        cudaStreamCreateWithFlags(&s2, cudaStreamNonBlocking);
        cudaEventCreateWithFlags(&e_fork, cudaEventDisableTiming);
        cudaEventCreateWithFlags(&e_join, cudaEventDisableTiming);
        init_done = 1;
    }

    const int T = 256;

    // all fp16 conversions in one launch (legacy stream)
    cvt_all_kernel<<<(CVT_S3 + T - 1) / T, T>>>(x, in_w, xp_w, out_w,
                                                (__half*)p_x1, (__half*)p_win1,
                                                (__half*)p_wxp1, (__half*)p_wout1);

    // fork: stream s2 waits for cvt, then computes the z-half of in_proj concurrently
    cudaEventRecord(e_fork, 0);
    cudaStreamWaitEvent(s2, e_fork, 0);

    // in_proj xs-half (cols 0..2047), legacy stream — conv depends only on this
    gemm_t128<1><<<dim3(DINNER / 128, NTOK / 128), 256, SMEMG>>>(
        (const __half*)p_x1, (const __half*)p_win1, p_xz,
        NTOK, 4096, DMODEL);

    // in_proj z-half (cols 2048..4095), stream s2 — needed only by scan
    gemm_t128<1><<<dim3(DINNER / 128, NTOK / 128), 256, SMEMG, s2>>>(
        (const __half*)p_x1, (const __half*)p_win1 + (size_t)DINNER * DMODEL,
        (void*)((__half*)p_xz + DINNER),
        NTOK, 4096, DMODEL);
    cudaEventRecord(e_join, s2);

    // middle chain on legacy stream overlaps the z-half GEMM
    conv_silu_kernel<<<((NTOK / 4) * (DINNER / 4)) / 256, 256>>>(
        (const __half*)p_xz, conv_w, conv_b, (__half*)p_xs1);

    gemm_xproj<<<dim3(XKS, NTOK / 128), 256, SMEMXP>>>(
        (const __half*)p_xs1, (const __half*)p_wxp1, (float*)p_bcp);
    reduce_bc_kernel<<<(NTOK * 32 / 4 + T - 1) / T, T>>>((const float*)p_bcp, (float*)p_bc);

    // join: scan needs the z-half
    cudaStreamWaitEvent(0, e_join, 0);

    scan_kernel<<<512, 128>>>((const __half*)p_xs1, (const __half*)p_xz, (const float*)p_bc,
                              A_log, Dp, (__half*)p_y1);

    // out_proj: [4096,2048] x [1024,2048]^T -> out [4096,1024] (fp32 output)
    gemm_t128<0><<<dim3(1024 / 128, NTOK / 128), 256, SMEMG>>>(
        (const __half*)p_y1, (const __half*)p_wout1, d_out,
        NTOK, 1024, DINNER);
}